// round 8
// baseline (speedup 1.0000x reference)
#include <cuda_runtime.h>
#include <cstdint>

// Problem constants (match reference)
#define B      32
#define TMAX   512
#define D      384
#define MAXDUR 8
#define TOUT   (TMAX * (MAXDUR - 1))   // 3584
#define VEC    (D / 4)                 // 96 float4 per row
#define ROWS_PER_CTA 8                 // 8 warps, 1 output row each
#define CTAS_PER_B   (TOUT / ROWS_PER_CTA)   // 448
#define NCTAS  (B * CTAS_PER_B)        // 14336

// ---------------------------------------------------------------------------
// Fused kernel — exact R4 structure (best measured: 29.4us), with one change:
// __stwt (write-through) stores instead of __stcs. The 176MB write stream no
// longer parks dirty in L2 (whose deferred writeback bursts into the next
// graph replay); it streams straight to DRAM.
//
// Each CTA (256 thr = 8 warps):
//   1. loads its batch's 512 durations, masks by ilen, block-scans to smem
//   2. all-zero fallback (cum[t] = min(t+1, L))
//   3. each warp binary-searches its frame (searchsorted right, 10 steps)
//   4. warp gathers 96 float4 of xs[b, idx, :] -> out row, write-through
// ---------------------------------------------------------------------------
__global__ void __launch_bounds__(256) lenreg_fused_kernel(
    const float4* __restrict__ xs,     // [B, TMAX, VEC]
    const int*    __restrict__ ds,     // [B, TMAX]
    const int*    __restrict__ ilens,  // [B]
    float4*       __restrict__ out)    // [B, TOUT, VEC]
{
    const int cta    = blockIdx.x;
    const int b      = cta / CTAS_PER_B;              // mul-shift
    const int f_base = (cta - b * CTAS_PER_B) * ROWS_PER_CTA;

    const int t    = threadIdx.x;     // 0..255
    const int lane = t & 31;
    const int wid  = t >> 5;          // 0..7

    __shared__ int s_cum[TMAX];       // inclusive cumsum of masked durations
    __shared__ int s_wsum[8];

    const int L = ilens[b];

    // --- block scan: thread t owns elements 2t, 2t+1 -----------------------
    const int e0 = 2 * t;
    const int e1 = 2 * t + 1;
    int d0 = (e0 < L) ? __ldg(ds + b * TMAX + e0) : 0;
    int d1 = (e1 < L) ? __ldg(ds + b * TMAX + e1) : 0;
    int pair = d0 + d1;

    // warp inclusive scan of pair sums
    int p = pair;
    #pragma unroll
    for (int off = 1; off < 32; off <<= 1) {
        int v = __shfl_up_sync(0xffffffffu, p, off);
        if (lane >= off) p += v;
    }
    if (lane == 31) s_wsum[wid] = p;
    __syncthreads();

    // cross-warp exclusive offset (8 values, scanned redundantly per thread)
    int woff = 0;
    #pragma unroll
    for (int w = 0; w < 8; ++w)
        woff += (w < wid) ? s_wsum[w] : 0;

    const int excl = p - pair + woff;     // exclusive prefix before e0
    s_cum[e0] = excl + d0;
    s_cum[e1] = excl + d0 + d1;
    __syncthreads();

    int total = s_cum[TMAX - 1];
    if (total == 0) {
        // all-zero fallback: d = mask -> cum[t'] = min(t'+1, L)
        s_cum[e0] = (e0 < L) ? (e0 + 1) : L;
        s_cum[e1] = (e1 < L) ? (e1 + 1) : L;
        total = L;                         // L >= 1 guaranteed
        __syncthreads();
    }

    // --- per-warp: binary search + gather -----------------------------------
    const int f = f_base + wid;            // this warp's output frame

    // searchsorted(cum, f, side='right'); 10 steps for range [0, 512]
    int lo = 0, hi = TMAX;
    #pragma unroll
    for (int step = 0; step < 10; ++step) {
        int mid = (lo + hi) >> 1;
        if (s_cum[mid] <= f) lo = mid + 1; else hi = mid;
    }
    const int idx = (lo < TMAX - 1) ? lo : (TMAX - 1);

    float4* dst = out + ((long)b * TOUT + f) * VEC;

    if (f < total) {
        const float4* src = xs + ((long)b * TMAX + idx) * VEC;
        float4 r0 = __ldg(src + lane);
        float4 r1 = __ldg(src + lane + 32);
        float4 r2 = __ldg(src + lane + 64);
        __stwt(dst + lane,      r0);
        __stwt(dst + lane + 32, r1);
        __stwt(dst + lane + 64, r2);
    } else {
        const float4 z = make_float4(0.f, 0.f, 0.f, 0.f);
        __stwt(dst + lane,      z);
        __stwt(dst + lane + 32, z);
        __stwt(dst + lane + 64, z);
    }
}

extern "C" void kernel_launch(void* const* d_in, const int* in_sizes, int n_in,
                              void* d_out, int out_size)
{
    const float* xs    = (const float*)d_in[0];  // [B, TMAX, D] fp32
    const int*   ds    = (const int*)  d_in[1];  // [B, TMAX] int32
    const int*   ilens = (const int*)  d_in[2];  // [B] int32
    float*       out   = (float*)d_out;          // [B, TOUT, D] fp32

    lenreg_fused_kernel<<<NCTAS, 256>>>(
        (const float4*)xs, ds, ilens, (float4*)out);
}

// round 9
// speedup vs baseline: 1.1017x; 1.1017x over previous
#include <cuda_runtime.h>
#include <cstdint>

// Problem constants (match reference)
#define B      32
#define TMAX   512
#define D      384
#define MAXDUR 8
#define TOUT   (TMAX * (MAXDUR - 1))   // 3584
#define VEC    (D / 4)                 // 96 float4 per row
#define NTHR   512                     // 16 warps
#define ROWS_PER_CTA 16                // 16 warps, 1 output row each
#define CTAS_PER_B   (TOUT / ROWS_PER_CTA)   // 224
#define NCTAS  (B * CTAS_PER_B)        // 7168

// ---------------------------------------------------------------------------
// Fused kernel: midpoint between R4 (8 rows/CTA, best 29.4us) and R5
// (32 rows/CTA, regressed via dual searches). 512 threads, 16 warps, one
// output row per warp, ONE binary search per warp, 3 independent float4
// loads + 3 __stcs per thread. Scan cost per row halved vs R4.
// ---------------------------------------------------------------------------
__global__ void __launch_bounds__(NTHR) lenreg_fused_kernel(
    const float4* __restrict__ xs,     // [B, TMAX, VEC]
    const int*    __restrict__ ds,     // [B, TMAX]
    const int*    __restrict__ ilens,  // [B]
    float4*       __restrict__ out)    // [B, TOUT, VEC]
{
    const int cta    = blockIdx.x;
    const int b      = cta / CTAS_PER_B;              // mul-shift
    const int f_base = (cta - b * CTAS_PER_B) * ROWS_PER_CTA;

    const int t    = threadIdx.x;     // 0..511
    const int lane = t & 31;
    const int wid  = t >> 5;          // 0..15

    __shared__ int s_cum[TMAX];       // inclusive cumsum of masked durations
    __shared__ int s_wsum[16];

    const int L = ilens[b];

    // --- block scan: thread t owns element t --------------------------------
    int d = (t < L) ? __ldg(ds + b * TMAX + t) : 0;

    int cum = d;
    #pragma unroll
    for (int off = 1; off < 32; off <<= 1) {
        int v = __shfl_up_sync(0xffffffffu, cum, off);
        if (lane >= off) cum += v;
    }
    if (lane == 31) s_wsum[wid] = cum;
    __syncthreads();

    if (wid == 0 && lane < 16) {
        int v = s_wsum[lane];
        #pragma unroll
        for (int off = 1; off < 16; off <<= 1) {
            int u = __shfl_up_sync(0x0000ffffu, v, off);
            if (lane >= off) v += u;
        }
        s_wsum[lane] = v;
    }
    __syncthreads();

    cum += (wid > 0) ? s_wsum[wid - 1] : 0;
    int total = s_wsum[15];

    if (total == 0) {
        // all-zero fallback: d = mask -> cum[t] = min(t+1, L)
        cum   = (t < L) ? (t + 1) : L;
        total = L;                         // L >= 1 guaranteed
    }
    s_cum[t] = cum;
    __syncthreads();

    // --- per-warp: one binary search + gather --------------------------------
    const int f = f_base + wid;            // this warp's output frame

    // searchsorted(cum, f, side='right'); 10 steps for range [0, 512]
    int lo = 0, hi = TMAX;
    #pragma unroll
    for (int step = 0; step < 10; ++step) {
        int mid = (lo + hi) >> 1;
        if (s_cum[mid] <= f) lo = mid + 1; else hi = mid;
    }
    const int idx = (lo < TMAX - 1) ? lo : (TMAX - 1);

    float4* dst = out + ((long)b * TOUT + f) * VEC;

    if (f < total) {
        const float4* src = xs + ((long)b * TMAX + idx) * VEC;
        float4 r0 = __ldg(src + lane);
        float4 r1 = __ldg(src + lane + 32);
        float4 r2 = __ldg(src + lane + 64);
        __stcs(dst + lane,      r0);
        __stcs(dst + lane + 32, r1);
        __stcs(dst + lane + 64, r2);
    } else {
        const float4 z = make_float4(0.f, 0.f, 0.f, 0.f);
        __stcs(dst + lane,      z);
        __stcs(dst + lane + 32, z);
        __stcs(dst + lane + 64, z);
    }
}

extern "C" void kernel_launch(void* const* d_in, const int* in_sizes, int n_in,
                              void* d_out, int out_size)
{
    const float* xs    = (const float*)d_in[0];  // [B, TMAX, D] fp32
    const int*   ds    = (const int*)  d_in[1];  // [B, TMAX] int32
    const int*   ilens = (const int*)  d_in[2];  // [B] int32
    float*       out   = (float*)d_out;          // [B, TOUT, D] fp32

    lenreg_fused_kernel<<<NCTAS, NTHR>>>(
        (const float4*)xs, ds, ilens, (float4*)out);
}

// round 10
// speedup vs baseline: 1.1888x; 1.0790x over previous
#include <cuda_runtime.h>
#include <cstdint>

// Problem constants (match reference)
#define B      32
#define TMAX   512
#define D      384
#define MAXDUR 8
#define TOUT   (TMAX * (MAXDUR - 1))   // 3584
#define VEC    (D / 4)                 // 96 float4 per row
#define ROWS_PER_CTA 8                 // 8 warps, 1 output row each
#define CTAS_PER_B   (TOUT / ROWS_PER_CTA)   // 448
#define NCTAS  (B * CTAS_PER_B)        // 14336

// ---------------------------------------------------------------------------
// Final kernel — R4 structure, best measured configuration (29.4us).
// Single fused kernel. Each CTA (256 thr = 8 warps):
//   1. loads its batch's 512 durations, masks by ilen, block-scans to smem cum
//   2. all-zero fallback (cum[t] = min(t+1, L))
//   3. each warp binary-searches its output frame f in cum (searchsorted right,
//      10 steps: insertion point range [0,512] needs ceil(log2(513)) = 10)
//   4. warp gathers 96 float4 of xs[b, idx, :] -> out row (streaming stores)
//
// Rationale (measured across R2-R9): the kernel is pinned at the HBM wall
// (201 MB mandatory traffic @ ~6.8 TB/s effective = 85% of spec). Issue/ALU
// utilization between 9% and 43% does not move the time; all structural
// variants (more rows/CTA, smem staging + bulk S2G, write-through stores,
// vectorized scan loads) measured 1-6us slower.
// ---------------------------------------------------------------------------
__global__ void __launch_bounds__(256) lenreg_fused_kernel(
    const float4* __restrict__ xs,     // [B, TMAX, VEC]
    const int*    __restrict__ ds,     // [B, TMAX]
    const int*    __restrict__ ilens,  // [B]
    float4*       __restrict__ out)    // [B, TOUT, VEC]
{
    const int cta    = blockIdx.x;
    const int b      = cta / CTAS_PER_B;              // mul-shift
    const int f_base = (cta - b * CTAS_PER_B) * ROWS_PER_CTA;

    const int t    = threadIdx.x;     // 0..255
    const int lane = t & 31;
    const int wid  = t >> 5;          // 0..7

    __shared__ int s_cum[TMAX];       // inclusive cumsum of masked durations
    __shared__ int s_wsum[8];

    const int L = ilens[b];

    // --- block scan: thread t owns elements 2t, 2t+1 --------------------
    const int e0 = 2 * t;
    const int e1 = 2 * t + 1;
    int d0 = (e0 < L) ? __ldg(ds + b * TMAX + e0) : 0;
    int d1 = (e1 < L) ? __ldg(ds + b * TMAX + e1) : 0;
    int pair = d0 + d1;

    // warp inclusive scan of pair sums
    int p = pair;
    #pragma unroll
    for (int off = 1; off < 32; off <<= 1) {
        int v = __shfl_up_sync(0xffffffffu, p, off);
        if (lane >= off) p += v;
    }
    if (lane == 31) s_wsum[wid] = p;
    __syncthreads();

    // cross-warp exclusive offset (8 values, scanned redundantly per thread)
    int woff = 0;
    #pragma unroll
    for (int w = 0; w < 8; ++w)
        woff += (w < wid) ? s_wsum[w] : 0;

    const int excl = p - pair + woff;     // exclusive prefix before e0
    s_cum[e0] = excl + d0;
    s_cum[e1] = excl + d0 + d1;
    __syncthreads();

    int total = s_cum[TMAX - 1];

    if (total == 0) {
        // all-zero fallback: d = mask -> cum[t'] = min(t'+1, L)
        s_cum[e0] = (e0 < L) ? (e0 + 1) : L;
        s_cum[e1] = (e1 < L) ? (e1 + 1) : L;
        total = L;                         // L >= 1 guaranteed
        __syncthreads();
    }

    // --- per-warp: binary search + gather --------------------------------
    const int f = f_base + wid;            // this warp's output frame

    // searchsorted(cum, f, side='right'): first idx with cum[idx] > f.
    // 10 iterations to fully collapse [0, 512] insertion range.
    int lo = 0, hi = TMAX;
    #pragma unroll
    for (int step = 0; step < 10; ++step) {
        int mid = (lo + hi) >> 1;
        if (s_cum[mid] <= f) lo = mid + 1; else hi = mid;
    }
    int idx = (lo < TMAX - 1) ? lo : (TMAX - 1);

    float4* dst = out + ((long)b * TOUT + f) * VEC;

    if (f < total) {
        const float4* src = xs + ((long)b * TMAX + idx) * VEC;
        float4 r0 = __ldg(src + lane);
        float4 r1 = __ldg(src + lane + 32);
        float4 r2 = __ldg(src + lane + 64);
        __stcs(dst + lane,      r0);
        __stcs(dst + lane + 32, r1);
        __stcs(dst + lane + 64, r2);
    } else {
        const float4 z = make_float4(0.f, 0.f, 0.f, 0.f);
        __stcs(dst + lane,      z);
        __stcs(dst + lane + 32, z);
        __stcs(dst + lane + 64, z);
    }
}

extern "C" void kernel_launch(void* const* d_in, const int* in_sizes, int n_in,
                              void* d_out, int out_size)
{
    const float* xs    = (const float*)d_in[0];  // [B, TMAX, D] fp32
    const int*   ds    = (const int*)  d_in[1];  // [B, TMAX] int32
    const int*   ilens = (const int*)  d_in[2];  // [B] int32
    float*       out   = (float*)d_out;          // [B, TOUT, D] fp32

    lenreg_fused_kernel<<<NCTAS, 256>>>(
        (const float4*)xs, ds, ilens, (float4*)out);
}